// round 14
// baseline (speedup 1.0000x reference)
#include <cuda_runtime.h>
#include <cuda_bf16.h>
#include <cuda_fp16.h>
#include <float.h>
#include <cstdint>

// Problem constants (fixed by setup_inputs)
#define Bv 4
#define Nv 16384
#define Dv 512
#define Sv 512
#define Mv (Bv * Nv)       // 65536 rows for fx/gx GEMM
#define MYv (Bv * Sv)      // 2048 rows for hy GEMM

// ---------------- scratch (device globals; no runtime allocation) ----------
__device__ float g_fx[(size_t)Mv * Dv];     // [B,N,D] 128 MiB
__device__ float g_gx[(size_t)Mv * Dv];     // [B,N,D] 128 MiB
__device__ float g_y [(size_t)MYv * Dv];    // [B,S,D] 4 MiB
__device__ float g_hy[(size_t)MYv * Dv];    // [B,S,D] 4 MiB
__device__ int   g_segstart[Sv + 1];

// ---------------- helpers ---------------------------------------------------
__device__ __forceinline__ uint32_t smem_to_u32(const void* p) {
    uint32_t a;
    asm("{ .reg .u64 t; cvta.to.shared.u64 t, %1; cvt.u32.u64 %0, t; }"
        : "=r"(a) : "l"(p));
    return a;
}
__device__ __forceinline__ void ldm_x4(uint32_t* r, uint32_t addr) {
    asm volatile("ldmatrix.sync.aligned.m8n8.x4.shared.b16 {%0,%1,%2,%3}, [%4];"
        : "=r"(r[0]), "=r"(r[1]), "=r"(r[2]), "=r"(r[3]) : "r"(addr));
}
__device__ __forceinline__ void mma_bf16(float* c, const uint32_t* a,
                                         uint32_t b0, uint32_t b1) {
    asm volatile(
        "mma.sync.aligned.m16n8k16.row.col.f32.bf16.bf16.f32 "
        "{%0,%1,%2,%3}, {%4,%5,%6,%7}, {%8,%9}, {%0,%1,%2,%3};"
        : "+f"(c[0]), "+f"(c[1]), "+f"(c[2]), "+f"(c[3])
        : "r"(a[0]), "r"(a[1]), "r"(a[2]), "r"(a[3]), "r"(b0), "r"(b1));
}
__device__ __forceinline__ void mma_f16(float* c, const uint32_t* a,
                                        uint32_t b0, uint32_t b1) {
    asm volatile(
        "mma.sync.aligned.m16n8k16.row.col.f32.f16.f16.f32 "
        "{%0,%1,%2,%3}, {%4,%5,%6,%7}, {%8,%9}, {%0,%1,%2,%3};"
        : "+f"(c[0]), "+f"(c[1]), "+f"(c[2]), "+f"(c[3])
        : "r"(a[0]), "r"(a[1]), "r"(a[2]), "r"(a[3]), "r"(b0), "r"(b1));
}

// ---------------- K0: segment boundaries from sorted jx (int32) ------------
__global__ void seg_bounds_kernel(const int* __restrict__ jx) {
    int n = blockIdx.x * blockDim.x + threadIdx.x;
    if (n > Nv) return;
    int cur  = (n < Nv) ? min(max(jx[n], 0), Sv - 1)     : Sv;
    int prev = (n > 0)  ? min(max(jx[n - 1], 0), Sv - 1) : -1;
    for (int s = prev + 1; s <= cur; ++s) g_segstart[s] = n;
}

// ---------------- K1: fp16 asymmetric 2-term mma GEMM (fx / gx) ------------
// out[m,e] = sum_d A[m,d]*W[e,d] + bias[e]; x single fp16, W split hi+lo fp16
// (W pre-scaled x256 so w_lo stays normal; /256 in epilogue).
#define TBK 16
#define ROWB 48                 // smem bytes per 16-half row (padded)
#define TILEB (128 * ROWB)      // 6144 B per matrix tile
#define BUFB16 (3 * TILEB)      // A, B_hi, B_lo
#define SMTOT16 (2 * BUFB16)    // 36864 B
#define WSCALE 256.0f
#define WINV   (1.0f / 256.0f)

__global__ __launch_bounds__(256, 1)
void gemm_f16_sel_kernel(const float* __restrict__ A, const float* __restrict__ W,
                         const float* __restrict__ bias, int out_sel) {
    extern __shared__ char sm[];
    float* out = (out_sel == 0) ? g_fx : g_gx;

    const int tid = threadIdx.x;
    const int wid = tid >> 5, lane = tid & 31;
    const int bm = blockIdx.y * 128, bn = blockIdx.x * 128;
    const int wm = (wid >> 2) * 64, wn = (wid & 3) * 32;
    const uint32_t sbase = smem_to_u32(sm);

    const int lrow = tid >> 1;
    const int lcol = (tid & 1) * 8;
    const float* gA = &A[(size_t)(bm + lrow) * Dv + lcol];
    const float* gW = &W[(size_t)(bn + lrow) * Dv + lcol];
    const uint32_t sts_off = (uint32_t)(lrow * ROWB + lcol * 2);

    float sa[8], sb[8];
    auto ldg = [&](int k0) {
        float4 v0 = *reinterpret_cast<const float4*>(gA + k0);
        float4 v1 = *reinterpret_cast<const float4*>(gA + k0 + 4);
        sa[0]=v0.x; sa[1]=v0.y; sa[2]=v0.z; sa[3]=v0.w;
        sa[4]=v1.x; sa[5]=v1.y; sa[6]=v1.z; sa[7]=v1.w;
        float4 w0 = *reinterpret_cast<const float4*>(gW + k0);
        float4 w1 = *reinterpret_cast<const float4*>(gW + k0 + 4);
        sb[0]=w0.x; sb[1]=w0.y; sb[2]=w0.z; sb[3]=w0.w;
        sb[4]=w1.x; sb[5]=w1.y; sb[6]=w1.z; sb[7]=w1.w;
    };
    auto sts = [&](int buf) {
        union { __half h[8]; uint4 u; } av, bhi, blo;
#pragma unroll
        for (int j = 0; j < 8; ++j) {
            av.h[j] = __float2half(sa[j]);
            float ws = sb[j] * WSCALE;
            __half h = __float2half(ws);
            bhi.h[j] = h;
            blo.h[j] = __float2half(ws - __half2float(h));
        }
        char* base = sm + buf * BUFB16 + sts_off;
        *reinterpret_cast<uint4*>(base)             = av.u;
        *reinterpret_cast<uint4*>(base + TILEB)     = bhi.u;
        *reinterpret_cast<uint4*>(base + 2 * TILEB) = blo.u;
    };

    float acc[4][4][4];
#pragma unroll
    for (int i = 0; i < 4; ++i)
#pragma unroll
        for (int j = 0; j < 4; ++j)
#pragma unroll
            for (int q = 0; q < 4; ++q) acc[i][j][q] = 0.f;

    const int lrow16 = lane & 15;
    const int ksel   = (lane >> 4) * 8;

    ldg(0);
    sts(0);
    __syncthreads();

    for (int ch = 0; ch < Dv / TBK; ++ch) {
        if (ch < Dv / TBK - 1) ldg((ch + 1) * TBK);

        const uint32_t abase = sbase + (ch & 1) * BUFB16;
        uint32_t af[4][4], bh[2][4], bl[2][4];
#pragma unroll
        for (int mi = 0; mi < 4; ++mi) {
            uint32_t ra = abase + (uint32_t)((wm + mi * 16 + lrow16) * ROWB + ksel * 2);
            ldm_x4(af[mi], ra);
        }
#pragma unroll
        for (int h = 0; h < 2; ++h) {
            uint32_t rb = abase + TILEB +
                          (uint32_t)((wn + h * 16 + lrow16) * ROWB + ksel * 2);
            ldm_x4(bh[h], rb);
            ldm_x4(bl[h], rb + TILEB);
        }
#pragma unroll
        for (int mi = 0; mi < 4; ++mi)
#pragma unroll
            for (int ni = 0; ni < 4; ++ni) {
                const int g = ni >> 1, s = ni & 1;
                mma_f16(acc[mi][ni], af[mi], bh[g][s], bh[g][s + 2]);
                mma_f16(acc[mi][ni], af[mi], bl[g][s], bl[g][s + 2]);
            }

        if (ch < Dv / TBK - 1) sts((ch + 1) & 1);
        __syncthreads();
    }

#pragma unroll
    for (int ni = 0; ni < 4; ++ni) {
        const int col = bn + wn + ni * 8 + (lane & 3) * 2;
        const float b0 = bias[col], b1 = bias[col + 1];
#pragma unroll
        for (int mi = 0; mi < 4; ++mi) {
            const int row = bm + wm + mi * 16 + (lane >> 2);
            float2 v0 = make_float2(acc[mi][ni][0] * WINV + b0,
                                    acc[mi][ni][1] * WINV + b1);
            float2 v1 = make_float2(acc[mi][ni][2] * WINV + b0,
                                    acc[mi][ni][3] * WINV + b1);
            *reinterpret_cast<float2*>(&out[(size_t)row * Dv + col]) = v0;
            *reinterpret_cast<float2*>(&out[(size_t)(row + 8) * Dv + col]) = v1;
        }
    }
}

// ---------------- K3: bf16 3-term mma GEMM (hy; small, high accuracy) ------
#define BUFB (4 * TILEB)
#define SMTOT (2 * BUFB)
__global__ __launch_bounds__(256, 1)
void gemm_bf16_kernel(const float* __restrict__ W, const float* __restrict__ bias) {
    extern __shared__ char sm[];
    const float* A = g_y;
    float* out = g_hy;

    const int tid = threadIdx.x;
    const int wid = tid >> 5, lane = tid & 31;
    const int bm = blockIdx.y * 128, bn = blockIdx.x * 128;
    const int wm = (wid >> 2) * 64, wn = (wid & 3) * 32;
    const uint32_t sbase = smem_to_u32(sm);

    const int lrow = tid >> 1;
    const int lcol = (tid & 1) * 8;
    const float* gA = &A[(size_t)(bm + lrow) * Dv + lcol];
    const float* gW = &W[(size_t)(bn + lrow) * Dv + lcol];
    const uint32_t sts_off = (uint32_t)(lrow * ROWB + lcol * 2);

    float sa[8], sb[8];
    auto ldg = [&](int k0) {
        float4 v0 = *reinterpret_cast<const float4*>(gA + k0);
        float4 v1 = *reinterpret_cast<const float4*>(gA + k0 + 4);
        sa[0]=v0.x; sa[1]=v0.y; sa[2]=v0.z; sa[3]=v0.w;
        sa[4]=v1.x; sa[5]=v1.y; sa[6]=v1.z; sa[7]=v1.w;
        float4 w0 = *reinterpret_cast<const float4*>(gW + k0);
        float4 w1 = *reinterpret_cast<const float4*>(gW + k0 + 4);
        sb[0]=w0.x; sb[1]=w0.y; sb[2]=w0.z; sb[3]=w0.w;
        sb[4]=w1.x; sb[5]=w1.y; sb[6]=w1.z; sb[7]=w1.w;
    };
    auto sts = [&](int buf) {
        union { __nv_bfloat16 h[8]; uint4 u; } ahi, alo, bhi, blo;
#pragma unroll
        for (int j = 0; j < 8; ++j) {
            __nv_bfloat16 h = __float2bfloat16(sa[j]);
            ahi.h[j] = h;
            alo.h[j] = __float2bfloat16(sa[j] - __bfloat162float(h));
            __nv_bfloat16 g = __float2bfloat16(sb[j]);
            bhi.h[j] = g;
            blo.h[j] = __float2bfloat16(sb[j] - __bfloat162float(g));
        }
        char* base = sm + buf * BUFB + sts_off;
        *reinterpret_cast<uint4*>(base)             = ahi.u;
        *reinterpret_cast<uint4*>(base + TILEB)     = alo.u;
        *reinterpret_cast<uint4*>(base + 2 * TILEB) = bhi.u;
        *reinterpret_cast<uint4*>(base + 3 * TILEB) = blo.u;
    };

    float acc[4][4][4];
#pragma unroll
    for (int i = 0; i < 4; ++i)
#pragma unroll
        for (int j = 0; j < 4; ++j)
#pragma unroll
            for (int q = 0; q < 4; ++q) acc[i][j][q] = 0.f;

    const int lrow16 = lane & 15;
    const int ksel   = (lane >> 4) * 8;

    ldg(0);
    sts(0);
    __syncthreads();

    for (int ch = 0; ch < Dv / TBK; ++ch) {
        if (ch < Dv / TBK - 1) ldg((ch + 1) * TBK);

        const uint32_t abase = sbase + (ch & 1) * BUFB;
        uint32_t a_hi[4][4], a_lo[4][4], bh[2][4], bl[2][4];
#pragma unroll
        for (int mi = 0; mi < 4; ++mi) {
            uint32_t ra = abase + (uint32_t)((wm + mi * 16 + lrow16) * ROWB + ksel * 2);
            ldm_x4(a_hi[mi], ra);
            ldm_x4(a_lo[mi], ra + TILEB);
        }
#pragma unroll
        for (int h = 0; h < 2; ++h) {
            uint32_t rb = abase + 2 * TILEB +
                          (uint32_t)((wn + h * 16 + lrow16) * ROWB + ksel * 2);
            ldm_x4(bh[h], rb);
            ldm_x4(bl[h], rb + TILEB);
        }
#pragma unroll
        for (int mi = 0; mi < 4; ++mi)
#pragma unroll
            for (int ni = 0; ni < 4; ++ni) {
                const int g = ni >> 1, s = ni & 1;
                mma_bf16(acc[mi][ni], a_hi[mi], bh[g][s], bh[g][s + 2]);
                mma_bf16(acc[mi][ni], a_hi[mi], bl[g][s], bl[g][s + 2]);
                mma_bf16(acc[mi][ni], a_lo[mi], bh[g][s], bh[g][s + 2]);
            }

        if (ch < Dv / TBK - 1) sts((ch + 1) & 1);
        __syncthreads();
    }

#pragma unroll
    for (int ni = 0; ni < 4; ++ni) {
        const int col = bn + wn + ni * 8 + (lane & 3) * 2;
        const float b0 = bias[col], b1 = bias[col + 1];
#pragma unroll
        for (int mi = 0; mi < 4; ++mi) {
            const int row = bm + wm + mi * 16 + (lane >> 2);
            float2 v0 = make_float2(acc[mi][ni][0] + b0, acc[mi][ni][1] + b1);
            float2 v1 = make_float2(acc[mi][ni][2] + b0, acc[mi][ni][3] + b1);
            *reinterpret_cast<float2*>(&out[(size_t)row * Dv + col]) = v0;
            *reinterpret_cast<float2*>(&out[(size_t)(row + 8) * Dv + col]) = v1;
        }
    }
}

// ---------------- K2: online (single-pass) segment softmax + weighted sum --
__global__ void segsoftagg_kernel() {
    const int s = blockIdx.x;
    const int b = blockIdx.y;
    const int n0 = g_segstart[s];
    const int n1 = g_segstart[s + 1];
    const int d = threadIdx.x * 4;

    float4 yv = make_float4(0.f, 0.f, 0.f, 0.f);
    if (n1 > n0) {
        float4 m = make_float4(-FLT_MAX, -FLT_MAX, -FLT_MAX, -FLT_MAX);
        float4 num = make_float4(0.f, 0.f, 0.f, 0.f);
        float4 den = make_float4(0.f, 0.f, 0.f, 0.f);
        const size_t base_b = (size_t)b * Nv * Dv;
        for (int n = n0; n < n1; ++n) {
            size_t off = base_b + (size_t)n * Dv + d;
            float4 g = *reinterpret_cast<const float4*>(&g_gx[off]);
            float4 f = *reinterpret_cast<const float4*>(&g_fx[off]);
            float nm, c, e;
            nm = fmaxf(m.x, g.x); c = __expf(m.x - nm); e = __expf(g.x - nm);
            den.x = den.x * c + e; num.x = num.x * c + e * f.x; m.x = nm;
            nm = fmaxf(m.y, g.y); c = __expf(m.y - nm); e = __expf(g.y - nm);
            den.y = den.y * c + e; num.y = num.y * c + e * f.y; m.y = nm;
            nm = fmaxf(m.z, g.z); c = __expf(m.z - nm); e = __expf(g.z - nm);
            den.z = den.z * c + e; num.z = num.z * c + e * f.z; m.z = nm;
            nm = fmaxf(m.w, g.w); c = __expf(m.w - nm); e = __expf(g.w - nm);
            den.w = den.w * c + e; num.w = num.w * c + e * f.w; m.w = nm;
        }
        yv.x = num.x / den.x; yv.y = num.y / den.y;
        yv.z = num.z / den.z; yv.w = num.w / den.w;
    }
    *reinterpret_cast<float4*>(&g_y[((size_t)b * Sv + s) * Dv + d]) = yv;
}

// ---------------- K4: gather out[b,n,:] = hy[b, jx[n], :] ------------------
__global__ void gather_kernel(const int* __restrict__ jx,
                              float* __restrict__ out) {
    int idx = blockIdx.x * blockDim.x + threadIdx.x;   // float4 index
    if (idx >= Bv * Nv * (Dv / 4)) return;
    int d4  = idx & (Dv / 4 - 1);
    int bn  = idx >> 7;            // D/4 = 128
    int n   = bn & (Nv - 1);
    int b   = bn >> 14;            // N = 16384
    int s   = min(max(jx[n], 0), Sv - 1);
    const float4* hy4 = reinterpret_cast<const float4*>(g_hy);
    reinterpret_cast<float4*>(out)[idx] = hy4[((size_t)(b * Sv + s)) * (Dv / 4) + d4];
}

// ---------------- host launcher --------------------------------------------
extern "C" void kernel_launch(void* const* d_in, const int* in_sizes, int n_in,
                              void* d_out, int out_size) {
    const float* x = nullptr;
    const int* jx = nullptr;
    const float *Wf = nullptr, *bf = nullptr, *Wg = nullptr, *bg = nullptr,
                *Wh = nullptr, *bh = nullptr;
    int wcnt = 0, bcnt = 0;
    for (int i = 0; i < n_in; ++i) {
        int sz = in_sizes[i];
        if (sz == Bv * Nv * Dv) {
            x = (const float*)d_in[i];
        } else if (sz == Nv) {
            jx = (const int*)d_in[i];
        } else if (sz == Dv * Dv) {
            if (wcnt == 0) Wf = (const float*)d_in[i];
            else if (wcnt == 1) Wg = (const float*)d_in[i];
            else Wh = (const float*)d_in[i];
            ++wcnt;
        } else if (sz == Dv) {
            if (bcnt == 0) bf = (const float*)d_in[i];
            else if (bcnt == 1) bg = (const float*)d_in[i];
            else bh = (const float*)d_in[i];
            ++bcnt;
        }
    }

    // K0: segment boundaries
    seg_bounds_kernel<<<(Nv + 1 + 255) / 256, 256>>>(jx);

    // K1: fx, gx via fp16 2-term mma GEMM
    cudaFuncSetAttribute(gemm_f16_sel_kernel,
                         cudaFuncAttributeMaxDynamicSharedMemorySize, SMTOT16);
    dim3 g1(Dv / 128, Mv / 128);
    gemm_f16_sel_kernel<<<g1, 256, SMTOT16>>>(x, Wf, bf, 0);
    gemm_f16_sel_kernel<<<g1, 256, SMTOT16>>>(x, Wg, bg, 1);

    // K2: online segment softmax + weighted sum -> g_y [B,S,D]
    dim3 g2(Sv, Bv);
    segsoftagg_kernel<<<g2, Dv / 4>>>();

    // K3: hy = y @ Wh^T + bh (bf16 3-term)
    cudaFuncSetAttribute(gemm_bf16_kernel,
                         cudaFuncAttributeMaxDynamicSharedMemorySize, SMTOT);
    dim3 g3(Dv / 128, MYv / 128);
    gemm_bf16_kernel<<<g3, 256, SMTOT>>>(Wh, bh);

    // K4: gather back to [B,N,D]
    int total4 = Bv * Nv * (Dv / 4);
    gather_kernel<<<(total4 + 255) / 256, 256>>>(jx, (float*)d_out);
}

// round 15
// speedup vs baseline: 1.0640x; 1.0640x over previous
#include <cuda_runtime.h>
#include <cuda_bf16.h>
#include <cuda_fp16.h>
#include <float.h>
#include <cstdint>

// Problem constants (fixed by setup_inputs)
#define Bv 4
#define Nv 16384
#define Dv 512
#define Sv 512
#define Mv (Bv * Nv)       // 65536 rows for fx/gx GEMM
#define MYv (Bv * Sv)      // 2048 rows for hy GEMM

// ---------------- scratch (device globals; no runtime allocation) ----------
__device__ float  g_fx[(size_t)Mv * Dv];    // 128 MiB
__device__ float  g_gx[(size_t)Mv * Dv];    // 128 MiB
__device__ float  g_y [(size_t)MYv * Dv];   // 4 MiB
__device__ float  g_hy[(size_t)MYv * Dv];   // 4 MiB
__device__ __half g_xh[(size_t)Mv * Dv];    // 64 MiB  (x in fp16)
__device__ __half g_wfhi[Dv * Dv], g_wflo[Dv * Dv];  // Wf*256 split
__device__ __half g_wghi[Dv * Dv], g_wglo[Dv * Dv];  // Wg*256 split
__device__ int    g_segstart[Sv + 1];

#define WSCALE 256.0f
#define WINV   (1.0f / 256.0f)

// ---------------- helpers ---------------------------------------------------
__device__ __forceinline__ uint32_t smem_to_u32(const void* p) {
    uint32_t a;
    asm("{ .reg .u64 t; cvta.to.shared.u64 t, %1; cvt.u32.u64 %0, t; }"
        : "=r"(a) : "l"(p));
    return a;
}
__device__ __forceinline__ void ldm_x4(uint32_t* r, uint32_t addr) {
    asm volatile("ldmatrix.sync.aligned.m8n8.x4.shared.b16 {%0,%1,%2,%3}, [%4];"
        : "=r"(r[0]), "=r"(r[1]), "=r"(r[2]), "=r"(r[3]) : "r"(addr));
}
__device__ __forceinline__ void mma_bf16(float* c, const uint32_t* a,
                                         uint32_t b0, uint32_t b1) {
    asm volatile(
        "mma.sync.aligned.m16n8k16.row.col.f32.bf16.bf16.f32 "
        "{%0,%1,%2,%3}, {%4,%5,%6,%7}, {%8,%9}, {%0,%1,%2,%3};"
        : "+f"(c[0]), "+f"(c[1]), "+f"(c[2]), "+f"(c[3])
        : "r"(a[0]), "r"(a[1]), "r"(a[2]), "r"(a[3]), "r"(b0), "r"(b1));
}
__device__ __forceinline__ void mma_f16(float* c, const uint32_t* a,
                                        uint32_t b0, uint32_t b1) {
    asm volatile(
        "mma.sync.aligned.m16n8k16.row.col.f32.f16.f16.f32 "
        "{%0,%1,%2,%3}, {%4,%5,%6,%7}, {%8,%9}, {%0,%1,%2,%3};"
        : "+f"(c[0]), "+f"(c[1]), "+f"(c[2]), "+f"(c[3])
        : "r"(a[0]), "r"(a[1]), "r"(a[2]), "r"(a[3]), "r"(b0), "r"(b1));
}
__device__ __forceinline__ void cp_async16(uint32_t dst, const void* src) {
    asm volatile("cp.async.cg.shared.global [%0], [%1], 16;"
        :: "r"(dst), "l"(src) : "memory");
}
#define CP_COMMIT()  asm volatile("cp.async.commit_group;" ::: "memory")
#define CP_WAIT1()   asm volatile("cp.async.wait_group 1;" ::: "memory")

// ---------------- K0: segment boundaries from sorted jx (int32) ------------
__global__ void seg_bounds_kernel(const int* __restrict__ jx) {
    int n = blockIdx.x * blockDim.x + threadIdx.x;
    if (n > Nv) return;
    int cur  = (n < Nv) ? min(max(jx[n], 0), Sv - 1)     : Sv;
    int prev = (n > 0)  ? min(max(jx[n - 1], 0), Sv - 1) : -1;
    for (int s = prev + 1; s <= cur; ++s) g_segstart[s] = n;
}

// ---------------- K_cvt: x -> fp16; Wf/Wg -> fp16 hi/lo (x256) -------------
__global__ void cvt_x_kernel(const float* __restrict__ x) {
    size_t i = (size_t)(blockIdx.x * blockDim.x + threadIdx.x) * 8;
    if (i >= (size_t)Mv * Dv) return;
    float4 v0 = *reinterpret_cast<const float4*>(x + i);
    float4 v1 = *reinterpret_cast<const float4*>(x + i + 4);
    union { __half h[8]; uint4 u; } o;
    o.h[0]=__float2half(v0.x); o.h[1]=__float2half(v0.y);
    o.h[2]=__float2half(v0.z); o.h[3]=__float2half(v0.w);
    o.h[4]=__float2half(v1.x); o.h[5]=__float2half(v1.y);
    o.h[6]=__float2half(v1.z); o.h[7]=__float2half(v1.w);
    *reinterpret_cast<uint4*>(&g_xh[i]) = o.u;
}
__global__ void cvt_w_kernel(const float* __restrict__ Wf,
                             const float* __restrict__ Wg) {
    int i = (blockIdx.x * blockDim.x + threadIdx.x) * 4;
    if (i >= Dv * Dv) return;
    float4 f = *reinterpret_cast<const float4*>(Wf + i);
    float4 g = *reinterpret_cast<const float4*>(Wg + i);
    union { __half h[4]; uint2 u; } fh, fl, gh, gl;
    float v[4] = {f.x, f.y, f.z, f.w};
    float w[4] = {g.x, g.y, g.z, g.w};
#pragma unroll
    for (int j = 0; j < 4; ++j) {
        float sf = v[j] * WSCALE;
        __half h = __float2half(sf);
        fh.h[j] = h; fl.h[j] = __float2half(sf - __half2float(h));
        float sg = w[j] * WSCALE;
        __half q = __float2half(sg);
        gh.h[j] = q; gl.h[j] = __float2half(sg - __half2float(q));
    }
    *reinterpret_cast<uint2*>(&g_wfhi[i]) = fh.u;
    *reinterpret_cast<uint2*>(&g_wflo[i]) = fl.u;
    *reinterpret_cast<uint2*>(&g_wghi[i]) = gh.u;
    *reinterpret_cast<uint2*>(&g_wglo[i]) = gl.u;
}

// ---------------- K1: fp16 cp.async pipelined GEMM (fx / gx) ---------------
// out[m,e] = (sum_d xh[m,d]*(Whi[e,d]+Wlo[e,d])) /256 + bias[e]
// CTA 128x128, 8 warps (2m x 4n), BK=32, 3-stage cp.async pipeline.
#define PITCH 80                      // 32 halfs (64 B) padded to 80 B
#define TILEP (128 * PITCH)           // 10240 B per tile
#define STAGEB (3 * TILEP)            // A, Bhi, Blo = 30720 B per stage
#define NSTAGE 3
#define SMPIPE (NSTAGE * STAGEB)      // 92160 B
#define NCH (Dv / 32)                 // 16 chunks

__global__ __launch_bounds__(256, 1)
void gemm_f16_pipe_kernel(const float* __restrict__ bias, int out_sel) {
    extern __shared__ char sm[];
    const __half* A   = g_xh;
    const __half* Bhi = (out_sel == 0) ? g_wfhi : g_wghi;
    const __half* Blo = (out_sel == 0) ? g_wflo : g_wglo;
    float* out = (out_sel == 0) ? g_fx : g_gx;

    const int tid = threadIdx.x;
    const int wid = tid >> 5, lane = tid & 31;
    const int bm = blockIdx.y * 128, bn = blockIdx.x * 128;
    const int wm = (wid >> 2) * 64, wn = (wid & 3) * 32;
    const uint32_t sbase = smem_to_u32(sm);

    // cp.async issue plan: 1536 granules/stage, 6 per thread
    // granule idx: tile = idx/512 (0=A,1=Bhi,2=Blo), r = (idx%512)/4, g = idx%4
    auto issue_stage = [&](int stage, int k0) {
        const uint32_t dbase = sbase + stage * STAGEB;
#pragma unroll
        for (int i = 0; i < 6; ++i) {
            const int idx = tid + i * 256;
            const int t = idx >> 9;
            const int r = (idx & 511) >> 2;
            const int g = idx & 3;
            const uint32_t dst = dbase + t * TILEP + r * PITCH + g * 16;
            const __half* src;
            if (t == 0)      src = &A  [(size_t)(bm + r) * Dv + k0 + g * 8];
            else if (t == 1) src = &Bhi[(size_t)(bn + r) * Dv + k0 + g * 8];
            else             src = &Blo[(size_t)(bn + r) * Dv + k0 + g * 8];
            cp_async16(dst, src);
        }
    };

    float acc[4][4][4];
#pragma unroll
    for (int i = 0; i < 4; ++i)
#pragma unroll
        for (int j = 0; j < 4; ++j)
#pragma unroll
            for (int q = 0; q < 4; ++q) acc[i][j][q] = 0.f;

    const int lrow16 = lane & 15;
    const int ksel   = (lane >> 4) * 8;   // half-index 0 or 8 within k16

    // prologue: stages 0,1
    issue_stage(0, 0);
    CP_COMMIT();
    issue_stage(1, 32);
    CP_COMMIT();

    for (int ch = 0; ch < NCH; ++ch) {
        CP_WAIT1();
        __syncthreads();
        if (ch + 2 < NCH) issue_stage((ch + 2) % NSTAGE, (ch + 2) * 32);
        CP_COMMIT();

        const uint32_t abase = sbase + (ch % NSTAGE) * STAGEB;
#pragma unroll
        for (int ks = 0; ks < 2; ++ks) {
            const uint32_t kb = (uint32_t)((ks * 16 + ksel) * 2);
            uint32_t af[4][4], bh[2][4], bl[2][4];
#pragma unroll
            for (int mi = 0; mi < 4; ++mi)
                ldm_x4(af[mi], abase + (uint32_t)((wm + mi * 16 + lrow16) * PITCH) + kb);
#pragma unroll
            for (int h = 0; h < 2; ++h) {
                const uint32_t rb = abase + TILEP +
                    (uint32_t)((wn + h * 16 + lrow16) * PITCH) + kb;
                ldm_x4(bh[h], rb);
                ldm_x4(bl[h], rb + TILEP);
            }
#pragma unroll
            for (int mi = 0; mi < 4; ++mi)
#pragma unroll
                for (int ni = 0; ni < 4; ++ni) {
                    const int g = ni >> 1, s = ni & 1;
                    mma_f16(acc[mi][ni], af[mi], bh[g][s], bh[g][s + 2]);
                    mma_f16(acc[mi][ni], af[mi], bl[g][s], bl[g][s + 2]);
                }
        }
    }

    // epilogue: /256 then +bias
#pragma unroll
    for (int ni = 0; ni < 4; ++ni) {
        const int col = bn + wn + ni * 8 + (lane & 3) * 2;
        const float b0 = bias[col], b1 = bias[col + 1];
#pragma unroll
        for (int mi = 0; mi < 4; ++mi) {
            const int row = bm + wm + mi * 16 + (lane >> 2);
            float2 v0 = make_float2(acc[mi][ni][0] * WINV + b0,
                                    acc[mi][ni][1] * WINV + b1);
            float2 v1 = make_float2(acc[mi][ni][2] * WINV + b0,
                                    acc[mi][ni][3] * WINV + b1);
            *reinterpret_cast<float2*>(&out[(size_t)row * Dv + col]) = v0;
            *reinterpret_cast<float2*>(&out[(size_t)(row + 8) * Dv + col]) = v1;
        }
    }
}

// ---------------- K3: bf16 3-term mma GEMM (hy; small, high accuracy) ------
#define TBK 16
#define ROWB 48
#define TILEB (128 * ROWB)
#define BUFB (4 * TILEB)
#define SMTOT (2 * BUFB)
__global__ __launch_bounds__(256, 1)
void gemm_bf16_kernel(const float* __restrict__ W, const float* __restrict__ bias) {
    extern __shared__ char sm[];
    const float* A = g_y;
    float* out = g_hy;

    const int tid = threadIdx.x;
    const int wid = tid >> 5, lane = tid & 31;
    const int bm = blockIdx.y * 128, bn = blockIdx.x * 128;
    const int wm = (wid >> 2) * 64, wn = (wid & 3) * 32;
    const uint32_t sbase = smem_to_u32(sm);

    const int lrow = tid >> 1;
    const int lcol = (tid & 1) * 8;
    const float* gA = &A[(size_t)(bm + lrow) * Dv + lcol];
    const float* gW = &W[(size_t)(bn + lrow) * Dv + lcol];
    const uint32_t sts_off = (uint32_t)(lrow * ROWB + lcol * 2);

    float sa[8], sb[8];
    auto ldg = [&](int k0) {
        float4 v0 = *reinterpret_cast<const float4*>(gA + k0);
        float4 v1 = *reinterpret_cast<const float4*>(gA + k0 + 4);
        sa[0]=v0.x; sa[1]=v0.y; sa[2]=v0.z; sa[3]=v0.w;
        sa[4]=v1.x; sa[5]=v1.y; sa[6]=v1.z; sa[7]=v1.w;
        float4 w0 = *reinterpret_cast<const float4*>(gW + k0);
        float4 w1 = *reinterpret_cast<const float4*>(gW + k0 + 4);
        sb[0]=w0.x; sb[1]=w0.y; sb[2]=w0.z; sb[3]=w0.w;
        sb[4]=w1.x; sb[5]=w1.y; sb[6]=w1.z; sb[7]=w1.w;
    };
    auto sts = [&](int buf) {
        union { __nv_bfloat16 h[8]; uint4 u; } ahi, alo, bhi, blo;
#pragma unroll
        for (int j = 0; j < 8; ++j) {
            __nv_bfloat16 h = __float2bfloat16(sa[j]);
            ahi.h[j] = h;
            alo.h[j] = __float2bfloat16(sa[j] - __bfloat162float(h));
            __nv_bfloat16 g = __float2bfloat16(sb[j]);
            bhi.h[j] = g;
            blo.h[j] = __float2bfloat16(sb[j] - __bfloat162float(g));
        }
        char* base = sm + buf * BUFB + sts_off;
        *reinterpret_cast<uint4*>(base)             = ahi.u;
        *reinterpret_cast<uint4*>(base + TILEB)     = alo.u;
        *reinterpret_cast<uint4*>(base + 2 * TILEB) = bhi.u;
        *reinterpret_cast<uint4*>(base + 3 * TILEB) = blo.u;
    };

    float acc[4][4][4];
#pragma unroll
    for (int i = 0; i < 4; ++i)
#pragma unroll
        for (int j = 0; j < 4; ++j)
#pragma unroll
            for (int q = 0; q < 4; ++q) acc[i][j][q] = 0.f;

    const int lrow16 = lane & 15;
    const int ksel   = (lane >> 4) * 8;

    ldg(0);
    sts(0);
    __syncthreads();

    for (int ch = 0; ch < Dv / TBK; ++ch) {
        if (ch < Dv / TBK - 1) ldg((ch + 1) * TBK);

        const uint32_t abase = sbase + (ch & 1) * BUFB;
        uint32_t a_hi[4][4], a_lo[4][4], bh[2][4], bl[2][4];
#pragma unroll
        for (int mi = 0; mi < 4; ++mi) {
            uint32_t ra = abase + (uint32_t)((wm + mi * 16 + lrow16) * ROWB + ksel * 2);
            ldm_x4(a_hi[mi], ra);
            ldm_x4(a_lo[mi], ra + TILEB);
        }
#pragma unroll
        for (int h = 0; h < 2; ++h) {
            uint32_t rb = abase + 2 * TILEB +
                          (uint32_t)((wn + h * 16 + lrow16) * ROWB + ksel * 2);
            ldm_x4(bh[h], rb);
            ldm_x4(bl[h], rb + TILEB);
        }
#pragma unroll
        for (int mi = 0; mi < 4; ++mi)
#pragma unroll
            for (int ni = 0; ni < 4; ++ni) {
                const int g = ni >> 1, s = ni & 1;
                mma_bf16(acc[mi][ni], a_hi[mi], bh[g][s], bh[g][s + 2]);
                mma_bf16(acc[mi][ni], a_hi[mi], bl[g][s], bl[g][s + 2]);
                mma_bf16(acc[mi][ni], a_lo[mi], bh[g][s], bh[g][s + 2]);
            }

        if (ch < Dv / TBK - 1) sts((ch + 1) & 1);
        __syncthreads();
    }

#pragma unroll
    for (int ni = 0; ni < 4; ++ni) {
        const int col = bn + wn + ni * 8 + (lane & 3) * 2;
        const float b0 = bias[col], b1 = bias[col + 1];
#pragma unroll
        for (int mi = 0; mi < 4; ++mi) {
            const int row = bm + wm + mi * 16 + (lane >> 2);
            float2 v0 = make_float2(acc[mi][ni][0] + b0, acc[mi][ni][1] + b1);
            float2 v1 = make_float2(acc[mi][ni][2] + b0, acc[mi][ni][3] + b1);
            *reinterpret_cast<float2*>(&out[(size_t)row * Dv + col]) = v0;
            *reinterpret_cast<float2*>(&out[(size_t)(row + 8) * Dv + col]) = v1;
        }
    }
}

// ---------------- K2: online (single-pass) segment softmax + weighted sum --
__global__ void segsoftagg_kernel() {
    const int s = blockIdx.x;
    const int b = blockIdx.y;
    const int n0 = g_segstart[s];
    const int n1 = g_segstart[s + 1];
    const int d = threadIdx.x * 4;

    float4 yv = make_float4(0.f, 0.f, 0.f, 0.f);
    if (n1 > n0) {
        float4 m = make_float4(-FLT_MAX, -FLT_MAX, -FLT_MAX, -FLT_MAX);
        float4 num = make_float4(0.f, 0.f, 0.f, 0.f);
        float4 den = make_float4(0.f, 0.f, 0.f, 0.f);
        const size_t base_b = (size_t)b * Nv * Dv;
        for (int n = n0; n < n1; ++n) {
            size_t off = base_b + (size_t)n * Dv + d;
            float4 g = *reinterpret_cast<const float4*>(&g_gx[off]);
            float4 f = *reinterpret_cast<const float4*>(&g_fx[off]);
            float nm, c, e;
            nm = fmaxf(m.x, g.x); c = __expf(m.x - nm); e = __expf(g.x - nm);
            den.x = den.x * c + e; num.x = num.x * c + e * f.x; m.x = nm;
            nm = fmaxf(m.y, g.y); c = __expf(m.y - nm); e = __expf(g.y - nm);
            den.y = den.y * c + e; num.y = num.y * c + e * f.y; m.y = nm;
            nm = fmaxf(m.z, g.z); c = __expf(m.z - nm); e = __expf(g.z - nm);
            den.z = den.z * c + e; num.z = num.z * c + e * f.z; m.z = nm;
            nm = fmaxf(m.w, g.w); c = __expf(m.w - nm); e = __expf(g.w - nm);
            den.w = den.w * c + e; num.w = num.w * c + e * f.w; m.w = nm;
        }
        yv.x = num.x / den.x; yv.y = num.y / den.y;
        yv.z = num.z / den.z; yv.w = num.w / den.w;
    }
    *reinterpret_cast<float4*>(&g_y[((size_t)b * Sv + s) * Dv + d]) = yv;
}

// ---------------- K4: gather out[b,n,:] = hy[b, jx[n], :] ------------------
__global__ void gather_kernel(const int* __restrict__ jx,
                              float* __restrict__ out) {
    int idx = blockIdx.x * blockDim.x + threadIdx.x;   // float4 index
    if (idx >= Bv * Nv * (Dv / 4)) return;
    int d4  = idx & (Dv / 4 - 1);
    int bn  = idx >> 7;            // D/4 = 128
    int n   = bn & (Nv - 1);
    int b   = bn >> 14;            // N = 16384
    int s   = min(max(jx[n], 0), Sv - 1);
    const float4* hy4 = reinterpret_cast<const float4*>(g_hy);
    reinterpret_cast<float4*>(out)[idx] = hy4[((size_t)(b * Sv + s)) * (Dv / 4) + d4];
}

// ---------------- host launcher --------------------------------------------
extern "C" void kernel_launch(void* const* d_in, const int* in_sizes, int n_in,
                              void* d_out, int out_size) {
    const float* x = nullptr;
    const int* jx = nullptr;
    const float *Wf = nullptr, *bf = nullptr, *Wg = nullptr, *bg = nullptr,
                *Wh = nullptr, *bh = nullptr;
    int wcnt = 0, bcnt = 0;
    for (int i = 0; i < n_in; ++i) {
        int sz = in_sizes[i];
        if (sz == Bv * Nv * Dv) {
            x = (const float*)d_in[i];
        } else if (sz == Nv) {
            jx = (const int*)d_in[i];
        } else if (sz == Dv * Dv) {
            if (wcnt == 0) Wf = (const float*)d_in[i];
            else if (wcnt == 1) Wg = (const float*)d_in[i];
            else Wh = (const float*)d_in[i];
            ++wcnt;
        } else if (sz == Dv) {
            if (bcnt == 0) bf = (const float*)d_in[i];
            else if (bcnt == 1) bg = (const float*)d_in[i];
            else bh = (const float*)d_in[i];
            ++bcnt;
        }
    }

    // K0: segment boundaries
    seg_bounds_kernel<<<(Nv + 1 + 255) / 256, 256>>>(jx);

    // K_cvt: x -> fp16; Wf/Wg -> hi/lo fp16
    cvt_x_kernel<<<(Mv * (Dv / 8) + 255) / 256 / 1, 256>>>(x);
    cvt_w_kernel<<<(Dv * Dv / 4 + 255) / 256, 256>>>(Wf, Wg);

    // K1: fx, gx via pipelined fp16 GEMM
    cudaFuncSetAttribute(gemm_f16_pipe_kernel,
                         cudaFuncAttributeMaxDynamicSharedMemorySize, SMPIPE);
    dim3 g1(Dv / 128, Mv / 128);
    gemm_f16_pipe_kernel<<<g1, 256, SMPIPE>>>(bf, 0);
    gemm_f16_pipe_kernel<<<g1, 256, SMPIPE>>>(bg, 1);

    // K2: online segment softmax + weighted sum -> g_y [B,S,D]
    dim3 g2(Sv, Bv);
    segsoftagg_kernel<<<g2, Dv / 4>>>();

    // K3: hy = y @ Wh^T + bh (bf16 3-term)
    cudaFuncSetAttribute(gemm_bf16_kernel,
                         cudaFuncAttributeMaxDynamicSharedMemorySize, SMTOT);
    dim3 g3(Dv / 128, MYv / 128);
    gemm_bf16_kernel<<<g3, 256, SMTOT>>>(Wh, bh);

    // K4: gather back to [B,N,D]
    int total4 = Bv * Nv * (Dv / 4);
    gather_kernel<<<(total4 + 255) / 256, 256>>>(jx, (float*)d_out);
}

// round 16
// speedup vs baseline: 1.6446x; 1.5457x over previous
#include <cuda_runtime.h>
#include <cuda_bf16.h>
#include <cuda_fp16.h>
#include <float.h>
#include <cstdint>

// Problem constants (fixed by setup_inputs)
#define Bv 4
#define Nv 16384
#define Dv 512
#define Sv 512
#define Mv (Bv * Nv)       // 65536 rows for fx/gx GEMM
#define MYv (Bv * Sv)      // 2048 rows for hy GEMM

// ---------------- scratch (device globals; no runtime allocation) ----------
__device__ float  g_fx[(size_t)Mv * Dv];    // 128 MiB
__device__ float  g_gx[(size_t)Mv * Dv];    // 128 MiB
__device__ float  g_y [(size_t)MYv * Dv];   // 4 MiB
__device__ float  g_hy[(size_t)MYv * Dv];   // 4 MiB
__device__ __half g_xh[(size_t)Mv * Dv];    // 64 MiB  (x in fp16)
__device__ __half g_wfhi[Dv * Dv], g_wflo[Dv * Dv];  // Wf*256 split
__device__ __half g_wghi[Dv * Dv], g_wglo[Dv * Dv];  // Wg*256 split
__device__ int    g_segstart[Sv + 1];

#define WSCALE 256.0f
#define WINV   (1.0f / 256.0f)

// ---------------- helpers ---------------------------------------------------
__device__ __forceinline__ uint32_t smem_to_u32(const void* p) {
    uint32_t a;
    asm("{ .reg .u64 t; cvta.to.shared.u64 t, %1; cvt.u32.u64 %0, t; }"
        : "=r"(a) : "l"(p));
    return a;
}
__device__ __forceinline__ void ldm_x4(uint32_t* r, uint32_t addr) {
    asm volatile("ldmatrix.sync.aligned.m8n8.x4.shared.b16 {%0,%1,%2,%3}, [%4];"
        : "=r"(r[0]), "=r"(r[1]), "=r"(r[2]), "=r"(r[3]) : "r"(addr));
}
__device__ __forceinline__ void mma_bf16(float* c, const uint32_t* a,
                                         uint32_t b0, uint32_t b1) {
    asm volatile(
        "mma.sync.aligned.m16n8k16.row.col.f32.bf16.bf16.f32 "
        "{%0,%1,%2,%3}, {%4,%5,%6,%7}, {%8,%9}, {%0,%1,%2,%3};"
        : "+f"(c[0]), "+f"(c[1]), "+f"(c[2]), "+f"(c[3])
        : "r"(a[0]), "r"(a[1]), "r"(a[2]), "r"(a[3]), "r"(b0), "r"(b1));
}
__device__ __forceinline__ void mma_f16(float* c, const uint32_t* a,
                                        uint32_t b0, uint32_t b1) {
    asm volatile(
        "mma.sync.aligned.m16n8k16.row.col.f32.f16.f16.f32 "
        "{%0,%1,%2,%3}, {%4,%5,%6,%7}, {%8,%9}, {%0,%1,%2,%3};"
        : "+f"(c[0]), "+f"(c[1]), "+f"(c[2]), "+f"(c[3])
        : "r"(a[0]), "r"(a[1]), "r"(a[2]), "r"(a[3]), "r"(b0), "r"(b1));
}
__device__ __forceinline__ void cp_async16(uint32_t dst, const void* src) {
    asm volatile("cp.async.cg.shared.global [%0], [%1], 16;"
        :: "r"(dst), "l"(src) : "memory");
}
#define CP_COMMIT()  asm volatile("cp.async.commit_group;" ::: "memory")
#define CP_WAIT1()   asm volatile("cp.async.wait_group 1;" ::: "memory")

// ---------------- K0: segment boundaries from sorted jx (int32) ------------
__global__ void seg_bounds_kernel(const int* __restrict__ jx) {
    int n = blockIdx.x * blockDim.x + threadIdx.x;
    if (n > Nv) return;
    int cur  = (n < Nv) ? min(max(jx[n], 0), Sv - 1)     : Sv;
    int prev = (n > 0)  ? min(max(jx[n - 1], 0), Sv - 1) : -1;
    for (int s = prev + 1; s <= cur; ++s) g_segstart[s] = n;
}

// ---------------- K_cvt: x -> fp16; Wf/Wg -> fp16 hi/lo (x256) -------------
__global__ void cvt_x_kernel(const float* __restrict__ x) {
    size_t i = (size_t)(blockIdx.x * blockDim.x + threadIdx.x) * 8;
    if (i >= (size_t)Mv * Dv) return;
    float4 v0 = *reinterpret_cast<const float4*>(x + i);
    float4 v1 = *reinterpret_cast<const float4*>(x + i + 4);
    union { __half h[8]; uint4 u; } o;
    o.h[0]=__float2half(v0.x); o.h[1]=__float2half(v0.y);
    o.h[2]=__float2half(v0.z); o.h[3]=__float2half(v0.w);
    o.h[4]=__float2half(v1.x); o.h[5]=__float2half(v1.y);
    o.h[6]=__float2half(v1.z); o.h[7]=__float2half(v1.w);
    *reinterpret_cast<uint4*>(&g_xh[i]) = o.u;
}
__global__ void cvt_w_kernel(const float* __restrict__ Wf,
                             const float* __restrict__ Wg) {
    int i = (blockIdx.x * blockDim.x + threadIdx.x) * 4;
    if (i >= Dv * Dv) return;
    float4 f = *reinterpret_cast<const float4*>(Wf + i);
    float4 g = *reinterpret_cast<const float4*>(Wg + i);
    union { __half h[4]; uint2 u; } fh, fl, gh, gl;
    float v[4] = {f.x, f.y, f.z, f.w};
    float w[4] = {g.x, g.y, g.z, g.w};
#pragma unroll
    for (int j = 0; j < 4; ++j) {
        float sf = v[j] * WSCALE;
        __half h = __float2half(sf);
        fh.h[j] = h; fl.h[j] = __float2half(sf - __half2float(h));
        float sg = w[j] * WSCALE;
        __half q = __float2half(sg);
        gh.h[j] = q; gl.h[j] = __float2half(sg - __half2float(q));
    }
    *reinterpret_cast<uint2*>(&g_wfhi[i]) = fh.u;
    *reinterpret_cast<uint2*>(&g_wflo[i]) = fl.u;
    *reinterpret_cast<uint2*>(&g_wghi[i]) = gh.u;
    *reinterpret_cast<uint2*>(&g_wglo[i]) = gl.u;
}

// ---------------- K1: fp16 cp.async pipelined GEMM (fx & gx in one launch) -
// out[m,e] = (sum_d xh[m,d]*(Whi[e,d]+Wlo[e,d])) /256 + bias[e]
// CTA 128x128, 8 warps (2m x 4n), BK=32, 3-stage cp.async pipeline.
// blockIdx.z selects fx (0) vs gx (1). 2 CTAs/SM for latency hiding.
#define PITCH 80                      // 32 halfs (64 B) padded to 80 B
#define TILEP (128 * PITCH)           // 10240 B per tile
#define STAGEB (3 * TILEP)            // A, Bhi, Blo = 30720 B per stage
#define NSTAGE 3
#define SMPIPE (NSTAGE * STAGEB)      // 92160 B
#define NCH (Dv / 32)                 // 16 chunks

__global__ __launch_bounds__(256, 2)
void gemm_f16_pipe_kernel(const float* __restrict__ bias_f,
                          const float* __restrict__ bias_g) {
    extern __shared__ char sm[];
    const int out_sel = blockIdx.z;
    const __half* A   = g_xh;
    const __half* Bhi = (out_sel == 0) ? g_wfhi : g_wghi;
    const __half* Blo = (out_sel == 0) ? g_wflo : g_wglo;
    const float* bias = (out_sel == 0) ? bias_f : bias_g;
    float* out = (out_sel == 0) ? g_fx : g_gx;

    const int tid = threadIdx.x;
    const int wid = tid >> 5, lane = tid & 31;
    const int bm = blockIdx.y * 128, bn = blockIdx.x * 128;
    const int wm = (wid >> 2) * 64, wn = (wid & 3) * 32;
    const uint32_t sbase = smem_to_u32(sm);

    // cp.async issue plan: 1536 granules/stage, 6 per thread
    auto issue_stage = [&](int stage, int k0) {
        const uint32_t dbase = sbase + stage * STAGEB;
#pragma unroll
        for (int i = 0; i < 6; ++i) {
            const int idx = tid + i * 256;
            const int t = idx >> 9;
            const int r = (idx & 511) >> 2;
            const int g = idx & 3;
            const uint32_t dst = dbase + t * TILEP + r * PITCH + g * 16;
            const __half* src;
            if (t == 0)      src = &A  [(size_t)(bm + r) * Dv + k0 + g * 8];
            else if (t == 1) src = &Bhi[(size_t)(bn + r) * Dv + k0 + g * 8];
            else             src = &Blo[(size_t)(bn + r) * Dv + k0 + g * 8];
            cp_async16(dst, src);
        }
    };

    float acc[4][4][4];
#pragma unroll
    for (int i = 0; i < 4; ++i)
#pragma unroll
        for (int j = 0; j < 4; ++j)
#pragma unroll
            for (int q = 0; q < 4; ++q) acc[i][j][q] = 0.f;

    const int lrow16 = lane & 15;
    const int ksel   = (lane >> 4) * 8;   // half-index 0 or 8 within k16

    // prologue: stages 0,1
    issue_stage(0, 0);
    CP_COMMIT();
    issue_stage(1, 32);
    CP_COMMIT();

    for (int ch = 0; ch < NCH; ++ch) {
        CP_WAIT1();
        __syncthreads();
        if (ch + 2 < NCH) issue_stage((ch + 2) % NSTAGE, (ch + 2) * 32);
        CP_COMMIT();

        const uint32_t abase = sbase + (ch % NSTAGE) * STAGEB;
#pragma unroll
        for (int ks = 0; ks < 2; ++ks) {
            const uint32_t kb = (uint32_t)((ks * 16 + ksel) * 2);
            uint32_t af[4][4], bh[2][4], bl[2][4];
#pragma unroll
            for (int mi = 0; mi < 4; ++mi)
                ldm_x4(af[mi], abase + (uint32_t)((wm + mi * 16 + lrow16) * PITCH) + kb);
#pragma unroll
            for (int h = 0; h < 2; ++h) {
                const uint32_t rb = abase + TILEP +
                    (uint32_t)((wn + h * 16 + lrow16) * PITCH) + kb;
                ldm_x4(bh[h], rb);
                ldm_x4(bl[h], rb + TILEP);
            }
#pragma unroll
            for (int mi = 0; mi < 4; ++mi)
#pragma unroll
                for (int ni = 0; ni < 4; ++ni) {
                    const int g = ni >> 1, s = ni & 1;
                    mma_f16(acc[mi][ni], af[mi], bh[g][s], bh[g][s + 2]);
                    mma_f16(acc[mi][ni], af[mi], bl[g][s], bl[g][s + 2]);
                }
        }
    }

    // epilogue: /256 then +bias
#pragma unroll
    for (int ni = 0; ni < 4; ++ni) {
        const int col = bn + wn + ni * 8 + (lane & 3) * 2;
        const float b0 = bias[col], b1 = bias[col + 1];
#pragma unroll
        for (int mi = 0; mi < 4; ++mi) {
            const int row = bm + wm + mi * 16 + (lane >> 2);
            float2 v0 = make_float2(acc[mi][ni][0] * WINV + b0,
                                    acc[mi][ni][1] * WINV + b1);
            float2 v1 = make_float2(acc[mi][ni][2] * WINV + b0,
                                    acc[mi][ni][3] * WINV + b1);
            *reinterpret_cast<float2*>(&out[(size_t)row * Dv + col]) = v0;
            *reinterpret_cast<float2*>(&out[(size_t)(row + 8) * Dv + col]) = v1;
        }
    }
}

// ---------------- K3: bf16 3-term mma GEMM (hy; small, high accuracy) ------
#define TBK 16
#define ROWB 48
#define TILEB (128 * ROWB)
#define BUFB (4 * TILEB)
#define SMTOT (2 * BUFB)
__global__ __launch_bounds__(256, 1)
void gemm_bf16_kernel(const float* __restrict__ W, const float* __restrict__ bias) {
    extern __shared__ char sm[];
    const float* A = g_y;
    float* out = g_hy;

    const int tid = threadIdx.x;
    const int wid = tid >> 5, lane = tid & 31;
    const int bm = blockIdx.y * 128, bn = blockIdx.x * 128;
    const int wm = (wid >> 2) * 64, wn = (wid & 3) * 32;
    const uint32_t sbase = smem_to_u32(sm);

    const int lrow = tid >> 1;
    const int lcol = (tid & 1) * 8;
    const float* gA = &A[(size_t)(bm + lrow) * Dv + lcol];
    const float* gW = &W[(size_t)(bn + lrow) * Dv + lcol];
    const uint32_t sts_off = (uint32_t)(lrow * ROWB + lcol * 2);

    float sa[8], sb[8];
    auto ldg = [&](int k0) {
        float4 v0 = *reinterpret_cast<const float4*>(gA + k0);
        float4 v1 = *reinterpret_cast<const float4*>(gA + k0 + 4);
        sa[0]=v0.x; sa[1]=v0.y; sa[2]=v0.z; sa[3]=v0.w;
        sa[4]=v1.x; sa[5]=v1.y; sa[6]=v1.z; sa[7]=v1.w;
        float4 w0 = *reinterpret_cast<const float4*>(gW + k0);
        float4 w1 = *reinterpret_cast<const float4*>(gW + k0 + 4);
        sb[0]=w0.x; sb[1]=w0.y; sb[2]=w0.z; sb[3]=w0.w;
        sb[4]=w1.x; sb[5]=w1.y; sb[6]=w1.z; sb[7]=w1.w;
    };
    auto sts = [&](int buf) {
        union { __nv_bfloat16 h[8]; uint4 u; } ahi, alo, bhi, blo;
#pragma unroll
        for (int j = 0; j < 8; ++j) {
            __nv_bfloat16 h = __float2bfloat16(sa[j]);
            ahi.h[j] = h;
            alo.h[j] = __float2bfloat16(sa[j] - __bfloat162float(h));
            __nv_bfloat16 g = __float2bfloat16(sb[j]);
            bhi.h[j] = g;
            blo.h[j] = __float2bfloat16(sb[j] - __bfloat162float(g));
        }
        char* base = sm + buf * BUFB + sts_off;
        *reinterpret_cast<uint4*>(base)             = ahi.u;
        *reinterpret_cast<uint4*>(base + TILEB)     = alo.u;
        *reinterpret_cast<uint4*>(base + 2 * TILEB) = bhi.u;
        *reinterpret_cast<uint4*>(base + 3 * TILEB) = blo.u;
    };

    float acc[4][4][4];
#pragma unroll
    for (int i = 0; i < 4; ++i)
#pragma unroll
        for (int j = 0; j < 4; ++j)
#pragma unroll
            for (int q = 0; q < 4; ++q) acc[i][j][q] = 0.f;

    const int lrow16 = lane & 15;
    const int ksel   = (lane >> 4) * 8;

    ldg(0);
    sts(0);
    __syncthreads();

    for (int ch = 0; ch < Dv / TBK; ++ch) {
        if (ch < Dv / TBK - 1) ldg((ch + 1) * TBK);

        const uint32_t abase = sbase + (ch & 1) * BUFB;
        uint32_t a_hi[4][4], a_lo[4][4], bh[2][4], bl[2][4];
#pragma unroll
        for (int mi = 0; mi < 4; ++mi) {
            uint32_t ra = abase + (uint32_t)((wm + mi * 16 + lrow16) * ROWB + ksel * 2);
            ldm_x4(a_hi[mi], ra);
            ldm_x4(a_lo[mi], ra + TILEB);
        }
#pragma unroll
        for (int h = 0; h < 2; ++h) {
            uint32_t rb = abase + 2 * TILEB +
                          (uint32_t)((wn + h * 16 + lrow16) * ROWB + ksel * 2);
            ldm_x4(bh[h], rb);
            ldm_x4(bl[h], rb + TILEB);
        }
#pragma unroll
        for (int mi = 0; mi < 4; ++mi)
#pragma unroll
            for (int ni = 0; ni < 4; ++ni) {
                const int g = ni >> 1, s = ni & 1;
                mma_bf16(acc[mi][ni], a_hi[mi], bh[g][s], bh[g][s + 2]);
                mma_bf16(acc[mi][ni], a_hi[mi], bl[g][s], bl[g][s + 2]);
                mma_bf16(acc[mi][ni], a_lo[mi], bh[g][s], bh[g][s + 2]);
            }

        if (ch < Dv / TBK - 1) sts((ch + 1) & 1);
        __syncthreads();
    }

#pragma unroll
    for (int ni = 0; ni < 4; ++ni) {
        const int col = bn + wn + ni * 8 + (lane & 3) * 2;
        const float b0 = bias[col], b1 = bias[col + 1];
#pragma unroll
        for (int mi = 0; mi < 4; ++mi) {
            const int row = bm + wm + mi * 16 + (lane >> 2);
            float2 v0 = make_float2(acc[mi][ni][0] + b0, acc[mi][ni][1] + b1);
            float2 v1 = make_float2(acc[mi][ni][2] + b0, acc[mi][ni][3] + b1);
            *reinterpret_cast<float2*>(&out[(size_t)row * Dv + col]) = v0;
            *reinterpret_cast<float2*>(&out[(size_t)(row + 8) * Dv + col]) = v1;
        }
    }
}

// ---------------- K2: online (single-pass) segment softmax + weighted sum --
__global__ void segsoftagg_kernel() {
    const int s = blockIdx.x;
    const int b = blockIdx.y;
    const int n0 = g_segstart[s];
    const int n1 = g_segstart[s + 1];
    const int d = threadIdx.x * 4;

    float4 yv = make_float4(0.f, 0.f, 0.f, 0.f);
    if (n1 > n0) {
        float4 m = make_float4(-FLT_MAX, -FLT_MAX, -FLT_MAX, -FLT_MAX);
        float4 num = make_float4(0.f, 0.f, 0.f, 0.f);
        float4 den = make_float4(0.f, 0.f, 0.f, 0.f);
        const size_t base_b = (size_t)b * Nv * Dv;
        for (int n = n0; n < n1; ++n) {
            size_t off = base_b + (size_t)n * Dv + d;
            float4 g = *reinterpret_cast<const float4*>(&g_gx[off]);
            float4 f = *reinterpret_cast<const float4*>(&g_fx[off]);
            float nm, c, e;
            nm = fmaxf(m.x, g.x); c = __expf(m.x - nm); e = __expf(g.x - nm);
            den.x = den.x * c + e; num.x = num.x * c + e * f.x; m.x = nm;
            nm = fmaxf(m.y, g.y); c = __expf(m.y - nm); e = __expf(g.y - nm);
            den.y = den.y * c + e; num.y = num.y * c + e * f.y; m.y = nm;
            nm = fmaxf(m.z, g.z); c = __expf(m.z - nm); e = __expf(g.z - nm);
            den.z = den.z * c + e; num.z = num.z * c + e * f.z; m.z = nm;
            nm = fmaxf(m.w, g.w); c = __expf(m.w - nm); e = __expf(g.w - nm);
            den.w = den.w * c + e; num.w = num.w * c + e * f.w; m.w = nm;
        }
        yv.x = num.x / den.x; yv.y = num.y / den.y;
        yv.z = num.z / den.z; yv.w = num.w / den.w;
    }
    *reinterpret_cast<float4*>(&g_y[((size_t)b * Sv + s) * Dv + d]) = yv;
}

// ---------------- K4: gather out[b,n,:] = hy[b, jx[n], :] ------------------
__global__ void gather_kernel(const int* __restrict__ jx,
                              float* __restrict__ out) {
    int idx = blockIdx.x * blockDim.x + threadIdx.x;   // float4 index
    if (idx >= Bv * Nv * (Dv / 4)) return;
    int d4  = idx & (Dv / 4 - 1);
    int bn  = idx >> 7;            // D/4 = 128
    int n   = bn & (Nv - 1);
    int b   = bn >> 14;            // N = 16384
    int s   = min(max(jx[n], 0), Sv - 1);
    const float4* hy4 = reinterpret_cast<const float4*>(g_hy);
    reinterpret_cast<float4*>(out)[idx] = hy4[((size_t)(b * Sv + s)) * (Dv / 4) + d4];
}

// ---------------- host launcher --------------------------------------------
extern "C" void kernel_launch(void* const* d_in, const int* in_sizes, int n_in,
                              void* d_out, int out_size) {
    const float* x = nullptr;
    const int* jx = nullptr;
    const float *Wf = nullptr, *bf = nullptr, *Wg = nullptr, *bg = nullptr,
                *Wh = nullptr, *bh = nullptr;
    int wcnt = 0, bcnt = 0;
    for (int i = 0; i < n_in; ++i) {
        int sz = in_sizes[i];
        if (sz == Bv * Nv * Dv) {
            x = (const float*)d_in[i];
        } else if (sz == Nv) {
            jx = (const int*)d_in[i];
        } else if (sz == Dv * Dv) {
            if (wcnt == 0) Wf = (const float*)d_in[i];
            else if (wcnt == 1) Wg = (const float*)d_in[i];
            else Wh = (const float*)d_in[i];
            ++wcnt;
        } else if (sz == Dv) {
            if (bcnt == 0) bf = (const float*)d_in[i];
            else if (bcnt == 1) bg = (const float*)d_in[i];
            else bh = (const float*)d_in[i];
            ++bcnt;
        }
    }

    // K0: segment boundaries
    seg_bounds_kernel<<<(Nv + 1 + 255) / 256, 256>>>(jx);

    // K_cvt: x -> fp16; Wf/Wg -> hi/lo fp16
    cvt_x_kernel<<<(Mv * (Dv / 8) + 255) / 256, 256>>>(x);
    cvt_w_kernel<<<(Dv * Dv / 4 + 255) / 256, 256>>>(Wf, Wg);

    // K1: fx & gx in one launch (blockIdx.z selects), 2 CTAs/SM
    cudaFuncSetAttribute(gemm_f16_pipe_kernel,
                         cudaFuncAttributeMaxDynamicSharedMemorySize, SMPIPE);
    dim3 g1(Dv / 128, Mv / 128, 2);
    gemm_f16_pipe_kernel<<<g1, 256, SMPIPE>>>(bf, bg);

    // K2: online segment softmax + weighted sum -> g_y [B,S,D]
    dim3 g2(Sv, Bv);
    segsoftagg_kernel<<<g2, Dv / 4>>>();

    // K3: hy = y @ Wh^T + bh (bf16 3-term)
    cudaFuncSetAttribute(gemm_bf16_kernel,
                         cudaFuncAttributeMaxDynamicSharedMemorySize, SMTOT);
    dim3 g3(Dv / 128, MYv / 128);
    gemm_bf16_kernel<<<g3, 256, SMTOT>>>(Wh, bh);

    // K4: gather back to [B,N,D]
    int total4 = Bv * Nv * (Dv / 4);
    gather_kernel<<<(total4 + 255) / 256, 256>>>(jx, (float*)d_out);
}